// round 11
// baseline (speedup 1.0000x reference)
#include <cuda_runtime.h>
#include <cuda_bf16.h>
#include <cstdint>
#include <cstddef>

// ---------------------------------------------------------------------------
// Problem constants
// ---------------------------------------------------------------------------
namespace {
constexpr int Bg    = 256;
constexpr int Hc    = 128;
constexpr int OUTF  = 32;
constexpr int NRFc  = 16;
constexpr int NUSER = 4096;    // Bg*16
constexpr int NAG   = 16384;   // Bg*64
constexpr int APAD  = 136;     // padded bf16 row stride (272 B)
constexpr int TILEB = 128 * APAD * 2;   // 34816 B per bf16 tile
constexpr int NTK1  = 512;
}

// ---------------------------------------------------------------------------
// Scratch (device globals — no allocation allowed)
// ---------------------------------------------------------------------------
__device__ float g_hu  [NUSER * Hc];
__device__ float g_hu2 [NUSER * Hc];
__device__ float g_ha  [NAG   * Hc];
__device__ float g_ha2 [NAG   * Hc];
__device__ float g_haF [NAG   * Hc];
__device__ float g_tmpu[NUSER * Hc];
__device__ float g_tmpa[NAG   * Hc];
__device__ float g_meanA[Bg * Hc];
__device__ float g_meanU[Bg * Hc];
__device__ float g_hag [Bg * Hc];
// Pre-transposed + hi/lo-split weights: 6 matrices of [n=128][k=128] bf16
__device__ __nv_bfloat16 g_wt_hi[6 * Hc * Hc];
__device__ __nv_bfloat16 g_wt_lo[6 * Hc * Hc];

// ---------------------------------------------------------------------------
// Helpers (verbatim from the 79.9us kernel)
// ---------------------------------------------------------------------------
__device__ __forceinline__ uint32_t smem_u32(const void* p) {
    uint32_t a;
    asm("{ .reg .u64 t; cvta.to.shared.u64 t, %1; cvt.u32.u64 %0, t; }"
        : "=r"(a) : "l"(p));
    return a;
}
__device__ __forceinline__ void ldsm4(uint32_t* r, uint32_t addr) {
    asm volatile("ldmatrix.sync.aligned.m8n8.x4.shared.b16 {%0,%1,%2,%3}, [%4];"
                 : "=r"(r[0]), "=r"(r[1]), "=r"(r[2]), "=r"(r[3]) : "r"(addr));
}
__device__ __forceinline__ void mma16816(float* d, const uint32_t* a, const uint32_t* b) {
    asm volatile(
        "mma.sync.aligned.m16n8k16.row.col.f32.bf16.bf16.f32 "
        "{%0,%1,%2,%3}, {%4,%5,%6,%7}, {%8,%9}, {%0,%1,%2,%3};"
        : "+f"(d[0]), "+f"(d[1]), "+f"(d[2]), "+f"(d[3])
        : "r"(a[0]), "r"(a[1]), "r"(a[2]), "r"(a[3]), "r"(b[0]), "r"(b[1]));
}
__device__ __forceinline__ uint32_t pack_bf2(__nv_bfloat16 a, __nv_bfloat16 b) {
    return (uint32_t)__bfloat16_as_ushort(a) | ((uint32_t)__bfloat16_as_ushort(b) << 16);
}
__device__ __forceinline__ void split2(float a, float b, uint32_t& hi, uint32_t& lo) {
    const __nv_bfloat16 h0 = __float2bfloat16(a), h1 = __float2bfloat16(b);
    hi = pack_bf2(h0, h1);
    lo = pack_bf2(__float2bfloat16(a - __bfloat162float(h0)),
                  __float2bfloat16(b - __bfloat162float(h1)));
}

// ---------------------------------------------------------------------------
// HMMA GEMM: tile 128x128, 4 warps (warp tile 64x64), 3-pass bf16 hi/lo split.
//   MODE 0: C = relu(A@W + b)               -> full store
//   MODE 1: C = relu((A + mean_in[g])@W+b)  -> full store  (g = row>>SHIFT)
//   MODE 2: output only per-group mean of relu(A@W+b)  (SHIFT=4 -> G=16, 6 -> G=64)
// Byte-identical to the 79.9us kernel (no MODE 3 — spill-free set only).
// ---------------------------------------------------------------------------
template<int MODE, int SHIFT>
__global__ __launch_bounds__(128, 1)
void gemm_mma(const float* __restrict__ A,
              const __nv_bfloat16* __restrict__ Wh,
              const __nv_bfloat16* __restrict__ Wl,
              const float* __restrict__ bias,
              const float* __restrict__ mean_in,
              float* __restrict__ outp)
{
    extern __shared__ char sm[];
    // tiles: Ah | Al | Bh | Bl, each 128 x APAD bf16
    char* pAh = sm;
    char* pAl = sm + TILEB;
    char* pBh = sm + 2 * TILEB;
    char* pBl = sm + 3 * TILEB;

    const int tid  = threadIdx.x;
    const int w    = tid >> 5, lane = tid & 31;
    const int row0 = blockIdx.x * 128;

    // ---- load B (pre-split [n][k] bf16) into padded smem
    {
        const uint4* wh = reinterpret_cast<const uint4*>(Wh);
        const uint4* wl = reinterpret_cast<const uint4*>(Wl);
        #pragma unroll
        for (int i = tid; i < 2048; i += 128) {           // 8-bf16 units
            const int n = i >> 4, k8 = i & 15;
            const uint32_t o = (uint32_t)(n * APAD * 2 + k8 * 16);
            *reinterpret_cast<uint4*>(pBh + o) = wh[i];
            *reinterpret_cast<uint4*>(pBl + o) = wl[i];
        }
    }
    // ---- load A (fp32, optional mean broadcast add), split hi/lo
    {
        #pragma unroll
        for (int i = tid; i < 2048; i += 128) {
            const int r = i >> 4, k = (i & 15) * 8;
            const float* ap = A + (size_t)(row0 + r) * Hc + k;
            float v[8];
            *reinterpret_cast<float4*>(&v[0]) = *reinterpret_cast<const float4*>(ap);
            *reinterpret_cast<float4*>(&v[4]) = *reinterpret_cast<const float4*>(ap + 4);
            if constexpr (MODE == 1) {
                const int g = (row0 + r) >> SHIFT;
                const float* mp = mean_in + g * Hc + k;
                float m[8];
                *reinterpret_cast<float4*>(&m[0]) = *reinterpret_cast<const float4*>(mp);
                *reinterpret_cast<float4*>(&m[4]) = *reinterpret_cast<const float4*>(mp + 4);
                #pragma unroll
                for (int j = 0; j < 8; ++j) v[j] += m[j];
            }
            uint32_t hb[4], lb[4];
            #pragma unroll
            for (int j = 0; j < 4; ++j) {
                const __nv_bfloat16 h0 = __float2bfloat16(v[2*j]);
                const __nv_bfloat16 h1 = __float2bfloat16(v[2*j+1]);
                const float r0 = v[2*j]   - __bfloat162float(h0);
                const float r1 = v[2*j+1] - __bfloat162float(h1);
                hb[j] = pack_bf2(h0, h1);
                lb[j] = pack_bf2(__float2bfloat16(r0), __float2bfloat16(r1));
            }
            const uint32_t o = (uint32_t)(r * APAD * 2 + (i & 15) * 16);
            *reinterpret_cast<uint4*>(pAh + o) = *reinterpret_cast<uint4*>(hb);
            *reinterpret_cast<uint4*>(pAl + o) = *reinterpret_cast<uint4*>(lb);
        }
    }
    __syncthreads();

    const uint32_t aAh = smem_u32(pAh), aAl = smem_u32(pAl);
    const uint32_t aBh = smem_u32(pBh), aBl = smem_u32(pBl);

    const int wm = w >> 1, wn = w & 1;
    const int m0 = wm * 64, n0 = wn * 64;

    // per-thread ldmatrix offsets (bytes)
    const int rr = lane & 7, quad = lane >> 3;
    const uint32_t a_off = (uint32_t)((m0 + rr + ((quad & 1) << 3)) * (APAD * 2)
                                      + ((quad & 2) << 3));          // +8 cols -> +16 B
    const uint32_t b_off = (uint32_t)((n0 + rr + ((quad >> 1) << 3)) * (APAD * 2)
                                      + ((quad & 1) << 4));          // +8 k -> +16 B

    float acc[4][8][4];
    #pragma unroll
    for (int mf = 0; mf < 4; ++mf)
        #pragma unroll
        for (int nf = 0; nf < 8; ++nf)
            acc[mf][nf][0] = acc[mf][nf][1] = acc[mf][nf][2] = acc[mf][nf][3] = 0.f;

    #pragma unroll
    for (int pass = 0; pass < 3; ++pass) {
        const uint32_t Ab = (pass == 2 ? aAl : aAh) + a_off;
        const uint32_t Bb = (pass == 1 ? aBl : aBh) + b_off;
        #pragma unroll
        for (int kc = 0; kc < 8; ++kc) {
            const uint32_t kb = (uint32_t)kc * 32;       // 16 bf16 = 32 B
            uint32_t af[4][4];
            #pragma unroll
            for (int mf = 0; mf < 4; ++mf)
                ldsm4(af[mf], Ab + (uint32_t)(mf * 16 * APAD * 2) + kb);
            uint32_t bf[8][2];
            #pragma unroll
            for (int p = 0; p < 4; ++p) {
                uint32_t t4[4];
                ldsm4(t4, Bb + (uint32_t)(p * 16 * APAD * 2) + kb);
                bf[2*p][0] = t4[0]; bf[2*p][1] = t4[1];
                bf[2*p+1][0] = t4[2]; bf[2*p+1][1] = t4[3];
            }
            #pragma unroll
            for (int mf = 0; mf < 4; ++mf)
                #pragma unroll
                for (int nf = 0; nf < 8; ++nf)
                    mma16816(acc[mf][nf], af[mf], bf[nf]);
        }
    }

    // ---- epilogue
    const int tq = lane & 3, gq = lane >> 2;     // C frag: rows gq/gq+8, cols 2tq/2tq+1
    float bv0[8], bv1[8];
    #pragma unroll
    for (int nf = 0; nf < 8; ++nf) {
        bv0[nf] = bias[n0 + nf * 8 + 2 * tq];
        bv1[nf] = bias[n0 + nf * 8 + 2 * tq + 1];
    }

    if constexpr (MODE <= 1) {
        #pragma unroll
        for (int mf = 0; mf < 4; ++mf) {
            const int r_lo = row0 + m0 + mf * 16 + gq;
            #pragma unroll
            for (int nf = 0; nf < 8; ++nf) {
                const int col = n0 + nf * 8 + 2 * tq;
                float2 lo, hi;
                lo.x = fmaxf(acc[mf][nf][0] + bv0[nf], 0.f);
                lo.y = fmaxf(acc[mf][nf][1] + bv1[nf], 0.f);
                hi.x = fmaxf(acc[mf][nf][2] + bv0[nf], 0.f);
                hi.y = fmaxf(acc[mf][nf][3] + bv1[nf], 0.f);
                *reinterpret_cast<float2*>(&outp[(size_t)r_lo * Hc + col]) = lo;
                *reinterpret_cast<float2*>(&outp[(size_t)(r_lo + 8) * Hc + col]) = hi;
            }
        }
    } else if constexpr (SHIFT == 4) {           // group = 16 rows = one m-frag
        #pragma unroll
        for (int mf = 0; mf < 4; ++mf) {
            const int grp = (row0 >> 4) + wm * 4 + mf;
            #pragma unroll
            for (int nf = 0; nf < 8; ++nf) {
                float s0 = fmaxf(acc[mf][nf][0] + bv0[nf], 0.f)
                         + fmaxf(acc[mf][nf][2] + bv0[nf], 0.f);
                float s1 = fmaxf(acc[mf][nf][1] + bv1[nf], 0.f)
                         + fmaxf(acc[mf][nf][3] + bv1[nf], 0.f);
                s0 += __shfl_xor_sync(0xffffffffu, s0, 4);
                s1 += __shfl_xor_sync(0xffffffffu, s1, 4);
                s0 += __shfl_xor_sync(0xffffffffu, s0, 8);
                s1 += __shfl_xor_sync(0xffffffffu, s1, 8);
                s0 += __shfl_xor_sync(0xffffffffu, s0, 16);
                s1 += __shfl_xor_sync(0xffffffffu, s1, 16);
                if (lane < 4) {
                    const int col = n0 + nf * 8 + 2 * lane;
                    float2 o2; o2.x = s0 * 0.0625f; o2.y = s1 * 0.0625f;
                    *reinterpret_cast<float2*>(&outp[grp * Hc + col]) = o2;
                }
            }
        }
    } else {                                     // group = 64 rows = one warp-tile M
        float s0[8], s1[8];
        #pragma unroll
        for (int nf = 0; nf < 8; ++nf) { s0[nf] = 0.f; s1[nf] = 0.f; }
        #pragma unroll
        for (int mf = 0; mf < 4; ++mf)
            #pragma unroll
            for (int nf = 0; nf < 8; ++nf) {
                s0[nf] += fmaxf(acc[mf][nf][0] + bv0[nf], 0.f)
                        + fmaxf(acc[mf][nf][2] + bv0[nf], 0.f);
                s1[nf] += fmaxf(acc[mf][nf][1] + bv1[nf], 0.f)
                        + fmaxf(acc[mf][nf][3] + bv1[nf], 0.f);
            }
        const int grp = (row0 >> 6) + wm;
        #pragma unroll
        for (int nf = 0; nf < 8; ++nf) {
            float a0 = s0[nf], a1 = s1[nf];
            a0 += __shfl_xor_sync(0xffffffffu, a0, 4);
            a1 += __shfl_xor_sync(0xffffffffu, a1, 4);
            a0 += __shfl_xor_sync(0xffffffffu, a0, 8);
            a1 += __shfl_xor_sync(0xffffffffu, a1, 8);
            a0 += __shfl_xor_sync(0xffffffffu, a0, 16);
            a1 += __shfl_xor_sync(0xffffffffu, a1, 16);
            if (lane < 4) {
                const int col = n0 + nf * 8 + 2 * lane;
                float2 o2; o2.x = a0 * (1.0f / 64.0f); o2.y = a1 * (1.0f / 64.0f);
                *reinterpret_cast<float2*>(&outp[grp * Hc + col]) = o2;
            }
        }
    }
}

// ---------------------------------------------------------------------------
// K1: weight prep (blocks 0..5) + stage1 (blocks 6..37)  [512 threads]
// Verified correct in R10.
// ---------------------------------------------------------------------------
__global__ __launch_bounds__(NTK1, 1)
void k1_prep_stage1(const float* W0, const float* W1, const float* W2,
                    const float* W3, const float* W4, const float* W5,
                    __nv_bfloat16* oh, __nv_bfloat16* ol,
                    const float* __restrict__ uf,
                    const float* __restrict__ W_ue, const float* __restrict__ b_ue,
                    const float* __restrict__ W_t,  const float* __restrict__ b_t,
                    float* __restrict__ hu, float* __restrict__ hag)
{
    extern __shared__ char smraw[];
    const int tid = threadIdx.x;

    if (blockIdx.x < 6) {
        float* st = reinterpret_cast<float*>(smraw);
        const int m = blockIdx.x;
        uint32_t* ph = reinterpret_cast<uint32_t*>(oh + (size_t)m * Hc * Hc);
        uint32_t* pl = reinterpret_cast<uint32_t*>(ol + (size_t)m * Hc * Hc);
        const float* Ws[6] = {W0, W1, W2, W3, W4, W5};
        const float* W = Ws[m];
        for (int i = tid; i < Hc * 32; i += NTK1) {
            const int kr = i >> 5, c4 = i & 31;
            *reinterpret_cast<float4*>(&st[kr * 132 + c4 * 4]) =
                reinterpret_cast<const float4*>(W)[i];
        }
        __syncthreads();
        for (int i = tid; i < Hc * 64; i += NTK1) {
            const int n = i >> 6, k2 = (i & 63) * 2;
            uint32_t hi, lo;
            split2(st[k2 * 132 + n], st[(k2 + 1) * 132 + n], hi, lo);
            ph[n * 64 + (i & 63)] = hi;
            pl[n * 64 + (i & 63)] = lo;
        }
        return;
    }

    // ---- stage1: hu = relu(uf@W_ue+b), per-16 mean, hag = relu(mean@W_t+b)
    float* sA    = reinterpret_cast<float*>(smraw);           // [128][36]
    float* sW    = reinterpret_cast<float*>(smraw + 18432);   // [32][128]
    float* spart = reinterpret_cast<float*>(smraw + 65536);   // [16][132]
    float* smean = reinterpret_cast<float*>(smraw + 73984);   // [8][132]
    float* sWt   = reinterpret_cast<float*>(smraw);           // phase2: [128][128]

    const int row0 = (blockIdx.x - 6) * 128;

    for (int i = tid; i < 1024; i += NTK1) {
        const int r = i >> 3, k4 = i & 7;
        *reinterpret_cast<float4*>(&sA[r * 36 + k4 * 4]) =
            reinterpret_cast<const float4*>(uf)[(size_t)row0 * 8 + i];
    }
    for (int i = tid; i < 1024; i += NTK1)
        reinterpret_cast<float4*>(sW)[i] = reinterpret_cast<const float4*>(W_ue)[i];
    __syncthreads();

    {
        const int tx = tid & 31, ty = tid >> 5;
        const float4 b4 = reinterpret_cast<const float4*>(b_ue)[tx];
        float4 msum = {0.f, 0.f, 0.f, 0.f};
        #pragma unroll 2
        for (int i = 0; i < 8; ++i) {
            const int r = ty * 8 + i;
            float4 acc = b4;
            #pragma unroll
            for (int k = 0; k < 32; ++k) {
                const float a = sA[r * 36 + k];
                const float4 w = reinterpret_cast<const float4*>(sW)[k * 32 + tx];
                acc.x += a * w.x; acc.y += a * w.y; acc.z += a * w.z; acc.w += a * w.w;
            }
            acc.x = fmaxf(acc.x, 0.f); acc.y = fmaxf(acc.y, 0.f);
            acc.z = fmaxf(acc.z, 0.f); acc.w = fmaxf(acc.w, 0.f);
            reinterpret_cast<float4*>(hu)[(size_t)(row0 + r) * 32 + tx] = acc;
            msum.x += acc.x; msum.y += acc.y; msum.z += acc.z; msum.w += acc.w;
        }
        *reinterpret_cast<float4*>(&spart[ty * 132 + tx * 4]) = msum;
    }
    __syncthreads();
    for (int i = tid; i < 1024; i += NTK1) {
        const int g = i >> 7, c = i & 127;
        smean[g * 132 + c] = (spart[(2*g) * 132 + c] + spart[(2*g+1) * 132 + c]) * 0.0625f;
    }
    __syncthreads();
    for (int i = tid; i < 4096; i += NTK1)
        reinterpret_cast<float4*>(sWt)[i] = reinterpret_cast<const float4*>(W_t)[i];
    __syncthreads();
    if (tid < 256) {
        const int gr = tid >> 5, col4 = tid & 31;
        float4 acc = reinterpret_cast<const float4*>(b_t)[col4];
        #pragma unroll 4
        for (int k = 0; k < 128; ++k) {
            const float a = smean[gr * 132 + k];
            const float4 w = reinterpret_cast<const float4*>(sWt)[k * 32 + col4];
            acc.x += a * w.x; acc.y += a * w.y; acc.z += a * w.z; acc.w += a * w.w;
        }
        acc.x = fmaxf(acc.x, 0.f); acc.y = fmaxf(acc.y, 0.f);
        acc.z = fmaxf(acc.z, 0.f); acc.w = fmaxf(acc.w, 0.f);
        reinterpret_cast<float4*>(hag)[(size_t)((blockIdx.x - 6) * 8 + gr) * 32 + col4] = acc;
    }
}

// ---------------------------------------------------------------------------
// ha[row] = hag[row/64] + noise[row]   (float4 granularity) — from 79.9us run
// ---------------------------------------------------------------------------
__global__ void expand_add(const float* __restrict__ hag,
                           const float* __restrict__ noise,
                           float* __restrict__ ha)
{
    const int idx = blockIdx.x * blockDim.x + threadIdx.x;
    const int k4 = idx & 31, row = idx >> 5, g = row >> 6;
    float4 n = reinterpret_cast<const float4*>(noise)[idx];
    const float4 h = reinterpret_cast<const float4*>(hag)[g * 32 + k4];
    n.x += h.x; n.y += h.y; n.z += h.z; n.w += h.w;
    reinterpret_cast<float4*>(ha)[idx] = n;
}

// ---------------------------------------------------------------------------
// final_norm — verbatim from the 79.9us kernel
// ---------------------------------------------------------------------------
__global__ __launch_bounds__(256)
void final_norm(const float* __restrict__ ha, const float* __restrict__ W,
                const float* __restrict__ bias, float* __restrict__ out)
{
    constexpr int TM = 32, PAD = 132;
    __shared__ float sA[TM * PAD];
    __shared__ float sW[Hc * OUTF];
    __shared__ float sF[TM * OUTF];

    const int tid = threadIdx.x;
    const int row0 = blockIdx.x * TM;
    {
        const float4* Wv = reinterpret_cast<const float4*>(W);
        float4* sWv = reinterpret_cast<float4*>(sW);
        #pragma unroll
        for (int i = tid; i < Hc * OUTF / 4; i += 256) sWv[i] = Wv[i];
    }
    {
        const float4* Av = reinterpret_cast<const float4*>(ha + (size_t)row0 * Hc);
        #pragma unroll
        for (int i = tid; i < TM * 32; i += 256) {
            const int r = i >> 5, k4 = i & 31;
            *reinterpret_cast<float4*>(&sA[r * PAD + k4 * 4]) = Av[i];
        }
    }
    __syncthreads();

    const int tx = tid & 7, ty = tid >> 3;
    float acc[4] = {0.f, 0.f, 0.f, 0.f};
    #pragma unroll 4
    for (int k = 0; k < Hc; ++k) {
        const float4 w4 = reinterpret_cast<const float4*>(sW)[k * 8 + tx];
        const float a = sA[ty * PAD + k];
        acc[0] += a * w4.x; acc[1] += a * w4.y;
        acc[2] += a * w4.z; acc[3] += a * w4.w;
    }
    const float4 b4 = *reinterpret_cast<const float4*>(&bias[tx * 4]);
    {
        float4 c;
        c.x = acc[0] + b4.x; c.y = acc[1] + b4.y;
        c.z = acc[2] + b4.z; c.w = acc[3] + b4.w;
        *reinterpret_cast<float4*>(&sF[ty * OUTF + tx * 4]) = c;
    }
    __syncthreads();
    #pragma unroll
    for (int i = tid; i < TM * NRFc; i += 256) {
        const int r = i & 15, row = i >> 4;
        const float re = sF[row * OUTF + r];
        const float im = sF[row * OUTF + r + NRFc];
        const float inv = rsqrtf(re * re + im * im);
        float2 o; o.x = re * inv; o.y = im * inv;
        reinterpret_cast<float2*>(out)[(size_t)(row0 + row) * NRFc + r] = o;
    }
}

// ---------------------------------------------------------------------------
// Host
// ---------------------------------------------------------------------------
extern "C" void kernel_launch(void* const* d_in, const int* in_sizes, int n_in,
                              void* d_out, int out_size)
{
    (void)in_sizes; (void)n_in; (void)out_size;

    const float* user_feat = (const float*)d_in[0];
    const float* noise     = (const float*)d_in[1];
    const float* W_ue     = (const float*)d_in[6],  *b_ue     = (const float*)d_in[7];
    const float* W_t      = (const float*)d_in[8],  *b_t      = (const float*)d_in[9];
    const float* b_aggr_a = (const float*)d_in[11];
    const float* b_self_a = (const float*)d_in[13];
    const float* b_comb_a = (const float*)d_in[15];
    const float* b_aggr_u = (const float*)d_in[17];
    const float* b_self_u = (const float*)d_in[19];
    const float* b_comb_u = (const float*)d_in[21];
    const float* W_norm   = (const float*)d_in[22], *b_norm   = (const float*)d_in[23];
    float* out = (float*)d_out;

    float *hu, *hu2, *ha, *ha2, *haF, *tmpu, *tmpa, *meanA, *meanU, *hag;
    __nv_bfloat16 *wth, *wtl;
    cudaGetSymbolAddress((void**)&hu,    g_hu);
    cudaGetSymbolAddress((void**)&hu2,   g_hu2);
    cudaGetSymbolAddress((void**)&ha,    g_ha);
    cudaGetSymbolAddress((void**)&ha2,   g_ha2);
    cudaGetSymbolAddress((void**)&haF,   g_haF);
    cudaGetSymbolAddress((void**)&tmpu,  g_tmpu);
    cudaGetSymbolAddress((void**)&tmpa,  g_tmpa);
    cudaGetSymbolAddress((void**)&meanA, g_meanA);
    cudaGetSymbolAddress((void**)&meanU, g_meanU);
    cudaGetSymbolAddress((void**)&hag,   g_hag);
    cudaGetSymbolAddress((void**)&wth,   g_wt_hi);
    cudaGetSymbolAddress((void**)&wtl,   g_wt_lo);

    constexpr int SM_MMA = 4 * TILEB;   // 139264
    constexpr int SM_K1  = 78208;

    cudaFuncSetAttribute((void*)k1_prep_stage1, cudaFuncAttributeMaxDynamicSharedMemorySize, SM_K1);
    cudaFuncSetAttribute((void*)gemm_mma<0,0>, cudaFuncAttributeMaxDynamicSharedMemorySize, SM_MMA);
    cudaFuncSetAttribute((void*)gemm_mma<1,6>, cudaFuncAttributeMaxDynamicSharedMemorySize, SM_MMA);
    cudaFuncSetAttribute((void*)gemm_mma<1,4>, cudaFuncAttributeMaxDynamicSharedMemorySize, SM_MMA);
    cudaFuncSetAttribute((void*)gemm_mma<2,4>, cudaFuncAttributeMaxDynamicSharedMemorySize, SM_MMA);
    cudaFuncSetAttribute((void*)gemm_mma<2,6>, cudaFuncAttributeMaxDynamicSharedMemorySize, SM_MMA);

    const __nv_bfloat16 *WH0 = wth + 0*16384, *WL0 = wtl + 0*16384;   // aggr_a
    const __nv_bfloat16 *WH1 = wth + 1*16384, *WL1 = wtl + 1*16384;   // self_a
    const __nv_bfloat16 *WH2 = wth + 2*16384, *WL2 = wtl + 2*16384;   // comb_a
    const __nv_bfloat16 *WH3 = wth + 3*16384, *WL3 = wtl + 3*16384;   // aggr_u
    const __nv_bfloat16 *WH4 = wth + 4*16384, *WL4 = wtl + 4*16384;   // self_u
    const __nv_bfloat16 *WH5 = wth + 5*16384, *WL5 = wtl + 5*16384;   // comb_u

    // L1: weight prep + stage1 (hu, hag)                     (grid 38)
    k1_prep_stage1<<<6 + NUSER/128, NTK1, SM_K1>>>(
        (const float*)d_in[10], (const float*)d_in[12], (const float*)d_in[14],
        (const float*)d_in[16], (const float*)d_in[18], (const float*)d_in[20],
        wth, wtl,
        user_feat, W_ue, b_ue, W_t, b_t, hu, hag);

    // L2: ha = repeat(hag,64) + noise
    expand_add<<<NAG*Hc/4/256, 256>>>(hag, noise, ha);

    // ---- conv 1 (identical to the 79.9us schedule) ----
    gemm_mma<2,4><<<NUSER/128, 128, SM_MMA>>>(hu,  WH0, WL0, b_aggr_a, nullptr, meanA); // m_a
    gemm_mma<0,0><<<NAG/128,   128, SM_MMA>>>(ha,  WH1, WL1, b_self_a, nullptr, tmpa);
    gemm_mma<1,6><<<NAG/128,   128, SM_MMA>>>(tmpa,WH2, WL2, b_comb_a, meanA,   ha2);
    gemm_mma<2,6><<<NAG/128,   128, SM_MMA>>>(ha,  WH3, WL3, b_aggr_u, nullptr, meanU); // m_u
    gemm_mma<0,0><<<NUSER/128, 128, SM_MMA>>>(hu,  WH4, WL4, b_self_u, nullptr, tmpu);
    gemm_mma<1,4><<<NUSER/128, 128, SM_MMA>>>(tmpu,WH5, WL5, b_comb_u, meanU,   hu2);

    // ---- conv 2 (agent branch only; user branch is dead code) ----
    gemm_mma<2,4><<<NUSER/128, 128, SM_MMA>>>(hu2, WH0, WL0, b_aggr_a, nullptr, meanA);
    gemm_mma<0,0><<<NAG/128,   128, SM_MMA>>>(ha2, WH1, WL1, b_self_a, nullptr, tmpa);
    gemm_mma<1,6><<<NAG/128,   128, SM_MMA>>>(tmpa,WH2, WL2, b_comb_a, meanA,   haF);

    // ---- final projection + normalize ----
    final_norm<<<NAG/32, 256>>>(haF, W_norm, b_norm, out);
}

// round 12
// speedup vs baseline: 1.6897x; 1.6897x over previous
#include <cuda_runtime.h>
#include <cuda_bf16.h>
#include <cstdint>
#include <cstddef>

// ---------------------------------------------------------------------------
// Problem constants
// ---------------------------------------------------------------------------
namespace {
constexpr int Bg    = 256;
constexpr int Hc    = 128;
constexpr int NRFc  = 16;
constexpr int NUSER = 4096;    // Bg*16
constexpr int NAG   = 16384;   // Bg*64
constexpr int APAD  = 136;     // bf16 elems per smem row
constexpr int ASTR  = APAD * 2; // 272 bytes
}

// ---------------------------------------------------------------------------
// Scratch (device globals — no allocation allowed)
// ---------------------------------------------------------------------------
__device__ float g_hu  [NUSER * Hc];
__device__ float g_hu2 [NUSER * Hc];
__device__ float g_ha2 [NAG   * Hc];
__device__ float g_meanA[Bg * Hc];
__device__ float g_meanU[Bg * Hc];
__device__ float g_hag [Bg * Hc];
// Pre-transposed + hi/lo-split weights: slots 0..5 = H x H, slot 6 = W_norm' (64x128 used)
__device__ __nv_bfloat16 g_wt_hi[7 * Hc * Hc];
__device__ __nv_bfloat16 g_wt_lo[7 * Hc * Hc];

// ---------------------------------------------------------------------------
// Helpers
// ---------------------------------------------------------------------------
__device__ __forceinline__ uint32_t smem_u32(const void* p) {
    uint32_t a;
    asm("{ .reg .u64 t; cvta.to.shared.u64 t, %1; cvt.u32.u64 %0, t; }"
        : "=r"(a) : "l"(p));
    return a;
}
__device__ __forceinline__ void ldsm4(uint32_t* r, uint32_t addr) {
    asm volatile("ldmatrix.sync.aligned.m8n8.x4.shared.b16 {%0,%1,%2,%3}, [%4];"
                 : "=r"(r[0]), "=r"(r[1]), "=r"(r[2]), "=r"(r[3]) : "r"(addr));
}
__device__ __forceinline__ void mma16816(float* d, const uint32_t* a, const uint32_t* b) {
    asm volatile(
        "mma.sync.aligned.m16n8k16.row.col.f32.bf16.bf16.f32 "
        "{%0,%1,%2,%3}, {%4,%5,%6,%7}, {%8,%9}, {%0,%1,%2,%3};"
        : "+f"(d[0]), "+f"(d[1]), "+f"(d[2]), "+f"(d[3])
        : "r"(a[0]), "r"(a[1]), "r"(a[2]), "r"(a[3]), "r"(b[0]), "r"(b[1]));
}
__device__ __forceinline__ uint32_t pack_bf2(__nv_bfloat16 a, __nv_bfloat16 b) {
    return (uint32_t)__bfloat16_as_ushort(a) | ((uint32_t)__bfloat16_as_ushort(b) << 16);
}
__device__ __forceinline__ void split2(float a, float b, uint32_t& hi, uint32_t& lo) {
    const __nv_bfloat16 h0 = __float2bfloat16(a), h1 = __float2bfloat16(b);
    hi = pack_bf2(h0, h1);
    lo = pack_bf2(__float2bfloat16(a - __bfloat162float(h0)),
                  __float2bfloat16(b - __bfloat162float(h1)));
}

// A tile load: fp32 (+optional hag broadcast, group = row>>6), hi/lo split to smem
template<int TM, bool ADD>
__device__ __forceinline__ void load_split_A(const float* __restrict__ A,
                                             const float* __restrict__ addv,
                                             int row0, char* pAh, char* pAl, int tid)
{
    #pragma unroll
    for (int i = tid; i < TM * 16; i += 256) {
        const int r = i >> 4, k = (i & 15) * 8;
        const float* ap = A + (size_t)(row0 + r) * Hc + k;
        float v[8];
        *reinterpret_cast<float4*>(&v[0]) = *reinterpret_cast<const float4*>(ap);
        *reinterpret_cast<float4*>(&v[4]) = *reinterpret_cast<const float4*>(ap + 4);
        if (ADD) {
            const float* mp = addv + ((row0 + r) >> 6) * Hc + k;
            float m[8];
            *reinterpret_cast<float4*>(&m[0]) = *reinterpret_cast<const float4*>(mp);
            *reinterpret_cast<float4*>(&m[4]) = *reinterpret_cast<const float4*>(mp + 4);
            #pragma unroll
            for (int j = 0; j < 8; ++j) v[j] += m[j];
        }
        uint32_t hb[4], lb[4];
        #pragma unroll
        for (int j = 0; j < 4; ++j) split2(v[2*j], v[2*j+1], hb[j], lb[j]);
        const uint32_t o = (uint32_t)(r * ASTR + (i & 15) * 16);
        *reinterpret_cast<uint4*>(pAh + o) = *reinterpret_cast<uint4*>(hb);
        *reinterpret_cast<uint4*>(pAl + o) = *reinterpret_cast<uint4*>(lb);
    }
}

template<int NROWS>
__device__ __forceinline__ void load_B(const __nv_bfloat16* __restrict__ Wh,
                                       const __nv_bfloat16* __restrict__ Wl,
                                       char* pBh, char* pBl, int tid)
{
    const uint4* wh = reinterpret_cast<const uint4*>(Wh);
    const uint4* wl = reinterpret_cast<const uint4*>(Wl);
    #pragma unroll
    for (int i = tid; i < NROWS * 16; i += 256) {
        const uint32_t o = (uint32_t)((i >> 4) * ASTR + (i & 15) * 16);
        *reinterpret_cast<uint4*>(pBh + o) = wh[i];
        *reinterpret_cast<uint4*>(pBl + o) = wl[i];
    }
}

// 3-pass hi/lo MMA over K=128: acc += (Ah+Al)@(Bh+Bl) minus Al*Bl
template<int MF, int NF>
__device__ __forceinline__ void mma_3p(uint32_t aAh, uint32_t aAl,
                                       uint32_t aBh, uint32_t aBl,
                                       uint32_t a_off, uint32_t b_off,
                                       float (*acc)[NF][4])
{
    #pragma unroll
    for (int pass = 0; pass < 3; ++pass) {
        const uint32_t Ab = (pass == 2 ? aAl : aAh) + a_off;
        const uint32_t Bb = (pass == 1 ? aBl : aBh) + b_off;
        #pragma unroll
        for (int kc = 0; kc < 8; ++kc) {
            const uint32_t kb = (uint32_t)kc * 32;
            uint32_t af[MF][4];
            #pragma unroll
            for (int mf = 0; mf < MF; ++mf)
                ldsm4(af[mf], Ab + (uint32_t)(mf * 16 * ASTR) + kb);
            uint32_t bfr[NF][2];
            #pragma unroll
            for (int p = 0; p < NF / 2; ++p) {
                uint32_t t[4];
                ldsm4(t, Bb + (uint32_t)(p * 16 * ASTR) + kb);
                bfr[2*p][0] = t[0]; bfr[2*p][1] = t[1];
                bfr[2*p+1][0] = t[2]; bfr[2*p+1][1] = t[3];
            }
            #pragma unroll
            for (int mf = 0; mf < MF; ++mf)
                #pragma unroll
                for (int nf = 0; nf < NF; ++nf)
                    mma16816(acc[mf][nf], af[mf], bfr[nf]);
        }
    }
}

// ---------------------------------------------------------------------------
// K1: weight prep (blocks 0..6) + stage1 (blocks 7..38).  Both bodies are
// verbatim from the 79.9us kernel's prep_w / stage1; only the blockIdx split
// is new.  256 threads.
// ---------------------------------------------------------------------------
__global__ __launch_bounds__(256, 1)
void k1_prep_stage1(const float* W0, const float* W1, const float* W2,
                    const float* W3, const float* W4, const float* W5,
                    const float* Wn,
                    __nv_bfloat16* oh, __nv_bfloat16* ol,
                    const float* __restrict__ uf,
                    const float* __restrict__ W_ue, const float* __restrict__ b_ue,
                    const float* __restrict__ W_t,  const float* __restrict__ b_t,
                    float* __restrict__ hu, float* __restrict__ hag)
{
    extern __shared__ char smraw[];
    const int tid = threadIdx.x;

    if (blockIdx.x < 7) {
        // ---- prep_w body (verbatim) ----
        float* st = reinterpret_cast<float*>(smraw);
        const int m = blockIdx.x;
        uint32_t* ph = reinterpret_cast<uint32_t*>(oh + (size_t)m * Hc * Hc);
        uint32_t* pl = reinterpret_cast<uint32_t*>(ol + (size_t)m * Hc * Hc);

        if (m < 6) {
            const float* Ws[6] = {W0, W1, W2, W3, W4, W5};
            const float* W = Ws[m];
            for (int i = tid; i < Hc * 32; i += 256) {
                const int kr = i >> 5, c4 = i & 31;
                *reinterpret_cast<float4*>(&st[kr * 132 + c4 * 4]) =
                    reinterpret_cast<const float4*>(W)[i];
            }
            __syncthreads();
            for (int i = tid; i < Hc * 64; i += 256) {
                const int n = i >> 6, k2 = (i & 63) * 2;
                const float a = st[k2 * 132 + n];
                const float b = st[(k2 + 1) * 132 + n];
                uint32_t hi, lo;
                split2(a, b, hi, lo);
                ph[n * 64 + (i & 63)] = hi;
                pl[n * 64 + (i & 63)] = lo;
            }
        } else {
            // W_norm [128][32]
            for (int i = tid; i < Hc * 8; i += 256) {
                const int kr = i >> 3, c4 = i & 7;
                *reinterpret_cast<float4*>(&st[kr * 36 + c4 * 4]) =
                    reinterpret_cast<const float4*>(Wn)[i];
            }
            __syncthreads();
            for (int i = tid; i < 64 * 64; i += 256) {
                const int rowp = i >> 6, k = (i & 63) * 2;
                uint32_t hi = 0, lo = 0;
                if (rowp < 32) {
                    const int n = (rowp & 1) * 16 + (rowp >> 1);
                    split2(st[k * 36 + n], st[(k + 1) * 36 + n], hi, lo);
                }
                ph[rowp * 64 + (i & 63)] = hi;
                pl[rowp * 64 + (i & 63)] = lo;
            }
        }
        return;
    }

    // ---- stage1 body (verbatim from the 79.9us kernel) ----
    float* sA    = reinterpret_cast<float*>(smraw);            // [128][36]
    float* sW    = reinterpret_cast<float*>(smraw + 18432);    // W_ue [32][128]
    float* smean = reinterpret_cast<float*>(smraw + 65536);    // [8][132]
    float* sWt   = reinterpret_cast<float*>(smraw);            // phase2: W_t [128][128]

    const int row0 = (blockIdx.x - 7) * 128;

    for (int i = tid; i < 1024; i += 256) {
        const int r = i >> 3, k4 = i & 7;
        *reinterpret_cast<float4*>(&sA[r * 36 + k4 * 4]) =
            reinterpret_cast<const float4*>(uf)[(size_t)row0 * 8 + i];
    }
    for (int i = tid; i < 1024; i += 256)
        reinterpret_cast<float4*>(sW)[i] = reinterpret_cast<const float4*>(W_ue)[i];
    __syncthreads();

    const int tx = tid & 31, ty = tid >> 5;
    const float4 b4 = reinterpret_cast<const float4*>(b_ue)[tx];
    float4 msum = {0.f, 0.f, 0.f, 0.f};
    #pragma unroll 4
    for (int i = 0; i < 16; ++i) {
        const int r = ty * 16 + i;
        float4 acc = b4;
        #pragma unroll
        for (int k = 0; k < 32; ++k) {
            const float a = sA[r * 36 + k];
            const float4 w = reinterpret_cast<const float4*>(sW)[k * 32 + tx];
            acc.x += a * w.x; acc.y += a * w.y; acc.z += a * w.z; acc.w += a * w.w;
        }
        acc.x = fmaxf(acc.x, 0.f); acc.y = fmaxf(acc.y, 0.f);
        acc.z = fmaxf(acc.z, 0.f); acc.w = fmaxf(acc.w, 0.f);
        reinterpret_cast<float4*>(hu)[(size_t)(row0 + r) * 32 + tx] = acc;
        msum.x += acc.x; msum.y += acc.y; msum.z += acc.z; msum.w += acc.w;
    }
    {
        float4 mv = {msum.x * 0.0625f, msum.y * 0.0625f,
                     msum.z * 0.0625f, msum.w * 0.0625f};
        *reinterpret_cast<float4*>(&smean[ty * 132 + tx * 4]) = mv;
    }
    __syncthreads();
    // phase 2
    for (int i = tid; i < 4096; i += 256)
        reinterpret_cast<float4*>(sWt)[i] = reinterpret_cast<const float4*>(W_t)[i];
    __syncthreads();
    {
        const int col4 = tid & 31, gr = tid >> 5;
        float4 acc = reinterpret_cast<const float4*>(b_t)[col4];
        #pragma unroll 4
        for (int k = 0; k < 128; ++k) {
            const float a = smean[gr * 132 + k];
            const float4 w = reinterpret_cast<const float4*>(sWt)[k * 32 + col4];
            acc.x += a * w.x; acc.y += a * w.y; acc.z += a * w.z; acc.w += a * w.w;
        }
        acc.x = fmaxf(acc.x, 0.f); acc.y = fmaxf(acc.y, 0.f);
        acc.z = fmaxf(acc.z, 0.f); acc.w = fmaxf(acc.w, 0.f);
        reinterpret_cast<float4*>(hag)[(size_t)((blockIdx.x - 7) * 8 + gr) * 32 + col4] = acc;
    }
}

// ---------------------------------------------------------------------------
// Single GEMM producing only the group mean of relu(A@W+b).   (verbatim)
//  OUTMODE 1: group=16 rows (per-mf). OUTMODE 2: group=64 rows (per warp-tile; TM=128).
// ---------------------------------------------------------------------------
template<int TM, bool ADD, int OUTMODE>
__global__ __launch_bounds__(256, 1)
void gemm_aggr(const float* __restrict__ A, const float* __restrict__ addv,
               const __nv_bfloat16* __restrict__ Wh, const __nv_bfloat16* __restrict__ Wl,
               const float* __restrict__ bias, float* __restrict__ outp)
{
    extern __shared__ char sm[];
    constexpr int TILEA = TM * ASTR;
    char* pAh = sm;
    char* pAl = sm + TILEA;
    char* pBh = sm + 2 * TILEA;
    char* pBl = pBh + 128 * ASTR;

    const int tid = threadIdx.x;
    const int row0 = blockIdx.x * TM;

    load_B<128>(Wh, Wl, pBh, pBl, tid);
    load_split_A<TM, ADD>(A, addv, row0, pAh, pAl, tid);
    __syncthreads();

    constexpr int WM = TM / 2, MF = WM / 16;
    const int w = tid >> 5, lane = tid & 31;
    const int wm = w >> 2, wn = w & 3;
    const int m0 = wm * WM, n0 = wn * 32;
    const int rr = lane & 7, quad = lane >> 3;
    const uint32_t a_off = (uint32_t)((m0 + rr + ((quad & 1) << 3)) * ASTR + ((quad & 2) << 3));
    const uint32_t b_off = (uint32_t)((n0 + rr + ((quad >> 1) << 3)) * ASTR + ((quad & 1) << 4));

    const uint32_t aAh = smem_u32(pAh), aAl = smem_u32(pAl);
    const uint32_t aBh = smem_u32(pBh), aBl = smem_u32(pBl);

    float acc[MF][4][4];
    #pragma unroll
    for (int mf = 0; mf < MF; ++mf)
        #pragma unroll
        for (int nf = 0; nf < 4; ++nf)
            acc[mf][nf][0] = acc[mf][nf][1] = acc[mf][nf][2] = acc[mf][nf][3] = 0.f;

    mma_3p<MF, 4>(aAh, aAl, aBh, aBl, a_off, b_off, acc);

    const int tq = lane & 3;
    float b0[4], b1[4];
    #pragma unroll
    for (int nf = 0; nf < 4; ++nf) {
        b0[nf] = bias[n0 + nf * 8 + 2 * tq];
        b1[nf] = bias[n0 + nf * 8 + 2 * tq + 1];
    }

    if (OUTMODE == 1) {
        #pragma unroll
        for (int mf = 0; mf < MF; ++mf) {
            const int grp = (row0 + m0 + mf * 16) >> 4;
            #pragma unroll
            for (int nf = 0; nf < 4; ++nf) {
                float s0 = fmaxf(acc[mf][nf][0] + b0[nf], 0.f)
                         + fmaxf(acc[mf][nf][2] + b0[nf], 0.f);
                float s1 = fmaxf(acc[mf][nf][1] + b1[nf], 0.f)
                         + fmaxf(acc[mf][nf][3] + b1[nf], 0.f);
                s0 += __shfl_xor_sync(~0u, s0, 4);  s1 += __shfl_xor_sync(~0u, s1, 4);
                s0 += __shfl_xor_sync(~0u, s0, 8);  s1 += __shfl_xor_sync(~0u, s1, 8);
                s0 += __shfl_xor_sync(~0u, s0, 16); s1 += __shfl_xor_sync(~0u, s1, 16);
                if (lane < 4) {
                    float2 o2 = {s0 * 0.0625f, s1 * 0.0625f};
                    *reinterpret_cast<float2*>(&outp[grp * Hc + n0 + nf * 8 + 2 * lane]) = o2;
                }
            }
        }
    } else {
        float s0[4] = {0,0,0,0}, s1[4] = {0,0,0,0};
        #pragma unroll
        for (int mf = 0; mf < MF; ++mf)
            #pragma unroll
            for (int nf = 0; nf < 4; ++nf) {
                s0[nf] += fmaxf(acc[mf][nf][0] + b0[nf], 0.f)
                        + fmaxf(acc[mf][nf][2] + b0[nf], 0.f);
                s1[nf] += fmaxf(acc[mf][nf][1] + b1[nf], 0.f)
                        + fmaxf(acc[mf][nf][3] + b1[nf], 0.f);
            }
        const int grp = (row0 + m0) >> 6;
        #pragma unroll
        for (int nf = 0; nf < 4; ++nf) {
            float a0 = s0[nf], a1 = s1[nf];
            a0 += __shfl_xor_sync(~0u, a0, 4);  a1 += __shfl_xor_sync(~0u, a1, 4);
            a0 += __shfl_xor_sync(~0u, a0, 8);  a1 += __shfl_xor_sync(~0u, a1, 8);
            a0 += __shfl_xor_sync(~0u, a0, 16); a1 += __shfl_xor_sync(~0u, a1, 16);
            if (lane < 4) {
                float2 o2 = {a0 * (1.f/64.f), a1 * (1.f/64.f)};
                *reinterpret_cast<float2*>(&outp[grp * Hc + n0 + nf * 8 + 2 * lane]) = o2;
            }
        }
    }
}

// ---------------------------------------------------------------------------
// Dual fused GEMM: out = relu( (relu(A@W1+b1) + mean[g]) @ W2 + b2 )  (verbatim)
//   MSHIFT: 6 (agent groups) or 4 (user groups)
// ---------------------------------------------------------------------------
template<int TM, bool ADD, int MSHIFT>
__global__ __launch_bounds__(256, 1)
void gemm_dual(const float* __restrict__ A, const float* __restrict__ addv,
               const __nv_bfloat16* __restrict__ W1h, const __nv_bfloat16* __restrict__ W1l,
               const float* __restrict__ b1,
               const float* __restrict__ meanv,
               const __nv_bfloat16* __restrict__ W2h, const __nv_bfloat16* __restrict__ W2l,
               const float* __restrict__ b2,
               float* __restrict__ outp)
{
    extern __shared__ char sm[];
    constexpr int TILEA = TM * ASTR;
    char* pAh = sm;
    char* pAl = sm + TILEA;
    char* pBh = sm + 2 * TILEA;
    char* pBl = pBh + 128 * ASTR;

    const int tid = threadIdx.x;
    const int row0 = blockIdx.x * TM;

    load_B<128>(W1h, W1l, pBh, pBl, tid);
    load_split_A<TM, ADD>(A, addv, row0, pAh, pAl, tid);
    __syncthreads();

    constexpr int WM = TM / 2, MF = WM / 16;
    const int w = tid >> 5, lane = tid & 31;
    const int wm = w >> 2, wn = w & 3;
    const int m0 = wm * WM, n0 = wn * 32;
    const int rr = lane & 7, quad = lane >> 3;
    const uint32_t a_off = (uint32_t)((m0 + rr + ((quad & 1) << 3)) * ASTR + ((quad & 2) << 3));
    const uint32_t b_off = (uint32_t)((n0 + rr + ((quad >> 1) << 3)) * ASTR + ((quad & 1) << 4));

    const uint32_t aAh = smem_u32(pAh), aAl = smem_u32(pAl);
    const uint32_t aBh = smem_u32(pBh), aBl = smem_u32(pBl);

    float acc[MF][4][4];
    #pragma unroll
    for (int mf = 0; mf < MF; ++mf)
        #pragma unroll
        for (int nf = 0; nf < 4; ++nf)
            acc[mf][nf][0] = acc[mf][nf][1] = acc[mf][nf][2] = acc[mf][nf][3] = 0.f;

    mma_3p<MF, 4>(aAh, aAl, aBh, aBl, a_off, b_off, acc);
    __syncthreads();   // all reads of A/B tiles done

    // epilogue1: e = relu(acc + b1) + mean ; re-split into A tiles
    const int tq = lane & 3, gq = lane >> 2;
    #pragma unroll
    for (int mf = 0; mf < MF; ++mf) {
        const int r0 = m0 + mf * 16 + gq;
        const int g = (MSHIFT == 6) ? ((row0 + m0) >> 6)
                                    : ((row0 + m0 + mf * 16) >> 4);
        #pragma unroll
        for (int nf = 0; nf < 4; ++nf) {
            const int c = n0 + nf * 8 + 2 * tq;
            const float2 mv = *reinterpret_cast<const float2*>(&meanv[g * Hc + c]);
            const float bb0 = b1[c], bb1 = b1[c + 1];
            const float e0 = fmaxf(acc[mf][nf][0] + bb0, 0.f) + mv.x;
            const float e1 = fmaxf(acc[mf][nf][1] + bb1, 0.f) + mv.y;
            const float e2 = fmaxf(acc[mf][nf][2] + bb0, 0.f) + mv.x;
            const float e3 = fmaxf(acc[mf][nf][3] + bb1, 0.f) + mv.y;
            uint32_t hi0, lo0, hi1, lo1;
            split2(e0, e1, hi0, lo0);
            split2(e2, e3, hi1, lo1);
            *reinterpret_cast<uint32_t*>(pAh + r0 * ASTR + c * 2) = hi0;
            *reinterpret_cast<uint32_t*>(pAl + r0 * ASTR + c * 2) = lo0;
            *reinterpret_cast<uint32_t*>(pAh + (r0 + 8) * ASTR + c * 2) = hi1;
            *reinterpret_cast<uint32_t*>(pAl + (r0 + 8) * ASTR + c * 2) = lo1;
        }
    }
    load_B<128>(W2h, W2l, pBh, pBl, tid);
    __syncthreads();

    #pragma unroll
    for (int mf = 0; mf < MF; ++mf)
        #pragma unroll
        for (int nf = 0; nf < 4; ++nf)
            acc[mf][nf][0] = acc[mf][nf][1] = acc[mf][nf][2] = acc[mf][nf][3] = 0.f;

    mma_3p<MF, 4>(aAh, aAl, aBh, aBl, a_off, b_off, acc);

    // epilogue2: full store relu(acc + b2)
    #pragma unroll
    for (int mf = 0; mf < MF; ++mf) {
        const int row = row0 + m0 + mf * 16 + gq;
        #pragma unroll
        for (int nf = 0; nf < 4; ++nf) {
            const int c = n0 + nf * 8 + 2 * tq;
            const float bb0 = b2[c], bb1 = b2[c + 1];
            float2 lo, hi;
            lo.x = fmaxf(acc[mf][nf][0] + bb0, 0.f);
            lo.y = fmaxf(acc[mf][nf][1] + bb1, 0.f);
            hi.x = fmaxf(acc[mf][nf][2] + bb0, 0.f);
            hi.y = fmaxf(acc[mf][nf][3] + bb1, 0.f);
            *reinterpret_cast<float2*>(&outp[(size_t)row * Hc + c]) = lo;
            *reinterpret_cast<float2*>(&outp[(size_t)(row + 8) * Hc + c]) = hi;
        }
    }
}

// ---------------------------------------------------------------------------
// Triple fused (conv2 agent + final)  (verbatim): A=ha2 ->
//   t = relu(A@W_self+b) + meanA[g]; h = relu(t@W_comb+b); f = h@W_norm'+b_norm;
//   out = (re,im)/|.| using the column-permuted W_norm'.   TM=128 fixed.
// ---------------------------------------------------------------------------
__global__ __launch_bounds__(256, 1)
void gemm_triple(const float* __restrict__ A,
                 const __nv_bfloat16* __restrict__ W1h, const __nv_bfloat16* __restrict__ W1l,
                 const float* __restrict__ b1,
                 const float* __restrict__ meanv,
                 const __nv_bfloat16* __restrict__ W2h, const __nv_bfloat16* __restrict__ W2l,
                 const float* __restrict__ b2,
                 const __nv_bfloat16* __restrict__ W3h, const __nv_bfloat16* __restrict__ W3l,
                 const float* __restrict__ b3,
                 float* __restrict__ outp)
{
    extern __shared__ char sm[];
    constexpr int TM = 128, TILEA = TM * ASTR;
    char* pAh = sm;
    char* pAl = sm + TILEA;
    char* pBh = sm + 2 * TILEA;
    char* pBl = pBh + 128 * ASTR;

    const int tid = threadIdx.x;
    const int row0 = blockIdx.x * TM;

    load_B<128>(W1h, W1l, pBh, pBl, tid);
    load_split_A<TM, false>(A, nullptr, row0, pAh, pAl, tid);
    __syncthreads();

    constexpr int MF = 4;
    const int w = tid >> 5, lane = tid & 31;
    const int wm = w >> 2, wn = w & 3;
    const int m0 = wm * 64, n0 = wn * 32;
    const int rr = lane & 7, quad = lane >> 3;
    const uint32_t a_off = (uint32_t)((m0 + rr + ((quad & 1) << 3)) * ASTR + ((quad & 2) << 3));
    const uint32_t b_off = (uint32_t)((n0 + rr + ((quad >> 1) << 3)) * ASTR + ((quad & 1) << 4));

    const uint32_t aAh = smem_u32(pAh), aAl = smem_u32(pAl);
    const uint32_t aBh = smem_u32(pBh), aBl = smem_u32(pBl);

    float acc[MF][4][4];
    #pragma unroll
    for (int mf = 0; mf < MF; ++mf)
        #pragma unroll
        for (int nf = 0; nf < 4; ++nf)
            acc[mf][nf][0] = acc[mf][nf][1] = acc[mf][nf][2] = acc[mf][nf][3] = 0.f;
    mma_3p<MF, 4>(aAh, aAl, aBh, aBl, a_off, b_off, acc);
    __syncthreads();

    const int tq = lane & 3, gq = lane >> 2;
    // epilogue1: relu + mean (shift 6), re-split
    #pragma unroll
    for (int mf = 0; mf < MF; ++mf) {
        const int r0 = m0 + mf * 16 + gq;
        const int g = (row0 + m0) >> 6;
        #pragma unroll
        for (int nf = 0; nf < 4; ++nf) {
            const int c = n0 + nf * 8 + 2 * tq;
            const float2 mv = *reinterpret_cast<const float2*>(&meanv[g * Hc + c]);
            const float bb0 = b1[c], bb1 = b1[c + 1];
            const float e0 = fmaxf(acc[mf][nf][0] + bb0, 0.f) + mv.x;
            const float e1 = fmaxf(acc[mf][nf][1] + bb1, 0.f) + mv.y;
            const float e2 = fmaxf(acc[mf][nf][2] + bb0, 0.f) + mv.x;
            const float e3 = fmaxf(acc[mf][nf][3] + bb1, 0.f) + mv.y;
            uint32_t hi0, lo0, hi1, lo1;
            split2(e0, e1, hi0, lo0);
            split2(e2, e3, hi1, lo1);
            *reinterpret_cast<uint32_t*>(pAh + r0 * ASTR + c * 2) = hi0;
            *reinterpret_cast<uint32_t*>(pAl + r0 * ASTR + c * 2) = lo0;
            *reinterpret_cast<uint32_t*>(pAh + (r0 + 8) * ASTR + c * 2) = hi1;
            *reinterpret_cast<uint32_t*>(pAl + (r0 + 8) * ASTR + c * 2) = lo1;
        }
    }
    load_B<128>(W2h, W2l, pBh, pBl, tid);
    __syncthreads();

    #pragma unroll
    for (int mf = 0; mf < MF; ++mf)
        #pragma unroll
        for (int nf = 0; nf < 4; ++nf)
            acc[mf][nf][0] = acc[mf][nf][1] = acc[mf][nf][2] = acc[mf][nf][3] = 0.f;
    mma_3p<MF, 4>(aAh, aAl, aBh, aBl, a_off, b_off, acc);
    __syncthreads();

    // epilogue2: relu(acc + b2) -> re-split
    #pragma unroll
    for (int mf = 0; mf < MF; ++mf) {
        const int r0 = m0 + mf * 16 + gq;
        #pragma unroll
        for (int nf = 0; nf < 4; ++nf) {
            const int c = n0 + nf * 8 + 2 * tq;
            const float bb0 = b2[c], bb1 = b2[c + 1];
            const float e0 = fmaxf(acc[mf][nf][0] + bb0, 0.f);
            const float e1 = fmaxf(acc[mf][nf][1] + bb1, 0.f);
            const float e2 = fmaxf(acc[mf][nf][2] + bb0, 0.f);
            const float e3 = fmaxf(acc[mf][nf][3] + bb1, 0.f);
            uint32_t hi0, lo0, hi1, lo1;
            split2(e0, e1, hi0, lo0);
            split2(e2, e3, hi1, lo1);
            *reinterpret_cast<uint32_t*>(pAh + r0 * ASTR + c * 2) = hi0;
            *reinterpret_cast<uint32_t*>(pAl + r0 * ASTR + c * 2) = lo0;
            *reinterpret_cast<uint32_t*>(pAh + (r0 + 8) * ASTR + c * 2) = hi1;
            *reinterpret_cast<uint32_t*>(pAl + (r0 + 8) * ASTR + c * 2) = lo1;
        }
    }
    load_B<64>(W3h, W3l, pBh, pBl, tid);
    __syncthreads();

    // MMA3: N = 64 (padded; real cols 0..31 = interleaved re/im pairs)
    const int n03 = wn * 16;
    const uint32_t b_off3 = (uint32_t)((n03 + rr + ((quad >> 1) << 3)) * ASTR + ((quad & 1) << 4));
    float acc3[MF][2][4];
    #pragma unroll
    for (int mf = 0; mf < MF; ++mf)
        #pragma unroll
        for (int nf = 0; nf < 2; ++nf)
            acc3[mf][nf][0] = acc3[mf][nf][1] = acc3[mf][nf][2] = acc3[mf][nf][3] = 0.f;
    mma_3p<MF, 2>(aAh, aAl, aBh, aBl, a_off, b_off3, acc3);

    if (wn < 2) {
        #pragma unroll
        for (int mf = 0; mf < MF; ++mf) {
            const int row = row0 + m0 + mf * 16 + gq;
            #pragma unroll
            for (int nf = 0; nf < 2; ++nf) {
                const int c = n03 + nf * 8 + 2 * tq;     // even; rf = c/2
                const int rf = c >> 1;
                const float br = b3[rf], bi = b3[rf + NRFc];
                {
                    const float re = acc3[mf][nf][0] + br;
                    const float im = acc3[mf][nf][1] + bi;
                    const float inv = rsqrtf(re * re + im * im);
                    float2 o = {re * inv, im * inv};
                    *reinterpret_cast<float2*>(&outp[(size_t)row * 32 + c]) = o;
                }
                {
                    const float re = acc3[mf][nf][2] + br;
                    const float im = acc3[mf][nf][3] + bi;
                    const float inv = rsqrtf(re * re + im * im);
                    float2 o = {re * inv, im * inv};
                    *reinterpret_cast<float2*>(&outp[(size_t)(row + 8) * 32 + c]) = o;
                }
            }
        }
    }
}

// ---------------------------------------------------------------------------
// Host
// ---------------------------------------------------------------------------
extern "C" void kernel_launch(void* const* d_in, const int* in_sizes, int n_in,
                              void* d_out, int out_size)
{
    (void)in_sizes; (void)n_in; (void)out_size;

    const float* user_feat = (const float*)d_in[0];
    const float* noise     = (const float*)d_in[1];
    const float* W_ue     = (const float*)d_in[6],  *b_ue     = (const float*)d_in[7];
    const float* W_t      = (const float*)d_in[8],  *b_t      = (const float*)d_in[9];
    const float* b_aggr_a = (const float*)d_in[11];
    const float* b_self_a = (const float*)d_in[13];
    const float* b_comb_a = (const float*)d_in[15];
    const float* b_aggr_u = (const float*)d_in[17];
    const float* b_self_u = (const float*)d_in[19];
    const float* b_comb_u = (const float*)d_in[21];
    const float* W_norm   = (const float*)d_in[22], *b_norm   = (const float*)d_in[23];
    float* out = (float*)d_out;

    float *hu, *hu2, *ha2, *meanA, *meanU, *hag;
    __nv_bfloat16 *wth, *wtl;
    cudaGetSymbolAddress((void**)&hu,    g_hu);
    cudaGetSymbolAddress((void**)&hu2,   g_hu2);
    cudaGetSymbolAddress((void**)&ha2,   g_ha2);
    cudaGetSymbolAddress((void**)&meanA, g_meanA);
    cudaGetSymbolAddress((void**)&meanU, g_meanU);
    cudaGetSymbolAddress((void**)&hag,   g_hag);
    cudaGetSymbolAddress((void**)&wth,   g_wt_hi);
    cudaGetSymbolAddress((void**)&wtl,   g_wt_lo);

    constexpr int SM_K1    = 69760;
    constexpr int SM_T64   = (2 * 64 + 2 * 128) * ASTR;       // 104448
    constexpr int SM_T128  = 4 * 128 * ASTR;                  // 139264

    cudaFuncSetAttribute((void*)k1_prep_stage1, cudaFuncAttributeMaxDynamicSharedMemorySize, SM_K1);
    cudaFuncSetAttribute((void*)gemm_aggr<64,false,1>, cudaFuncAttributeMaxDynamicSharedMemorySize, SM_T64);
    cudaFuncSetAttribute((void*)gemm_aggr<128,true,2>, cudaFuncAttributeMaxDynamicSharedMemorySize, SM_T128);
    cudaFuncSetAttribute((void*)gemm_dual<128,true,6>, cudaFuncAttributeMaxDynamicSharedMemorySize, SM_T128);
    cudaFuncSetAttribute((void*)gemm_dual<64,false,4>, cudaFuncAttributeMaxDynamicSharedMemorySize, SM_T64);
    cudaFuncSetAttribute((void*)gemm_triple, cudaFuncAttributeMaxDynamicSharedMemorySize, SM_T128);

    const __nv_bfloat16 *WH0 = wth + 0*16384, *WL0 = wtl + 0*16384;   // aggr_a
    const __nv_bfloat16 *WH1 = wth + 1*16384, *WL1 = wtl + 1*16384;   // self_a
    const __nv_bfloat16 *WH2 = wth + 2*16384, *WL2 = wtl + 2*16384;   // comb_a
    const __nv_bfloat16 *WH3 = wth + 3*16384, *WL3 = wtl + 3*16384;   // aggr_u
    const __nv_bfloat16 *WH4 = wth + 4*16384, *WL4 = wtl + 4*16384;   // self_u
    const __nv_bfloat16 *WH5 = wth + 5*16384, *WL5 = wtl + 5*16384;   // comb_u
    const __nv_bfloat16 *WH6 = wth + 6*16384, *WL6 = wtl + 6*16384;   // W_norm'

    // 1) weight prep (blocks 0..6) + stage1 (blocks 7..38)
    k1_prep_stage1<<<7 + NUSER/128, 256, SM_K1>>>(
        (const float*)d_in[10], (const float*)d_in[12], (const float*)d_in[14],
        (const float*)d_in[16], (const float*)d_in[18], (const float*)d_in[20],
        W_norm, wth, wtl,
        user_feat, W_ue, b_ue, W_t, b_t, hu, hag);
    // 2) conv1: meanA = mean16(relu(hu @ W_aggr_a + b))
    gemm_aggr<64,false,1><<<NUSER/64, 256, SM_T64>>>(hu, nullptr, WH0, WL0, b_aggr_a, meanA);
    // 3) conv1 agent: ha2 = relu((relu((noise+hag)@W_self_a+b) + meanA) @ W_comb_a + b)
    gemm_dual<128,true,6><<<NAG/128, 256, SM_T128>>>(noise, hag, WH1, WL1, b_self_a,
                                                     meanA, WH2, WL2, b_comb_a, ha2);
    // 4) conv1: meanU = mean64(relu((noise+hag) @ W_aggr_u + b))
    gemm_aggr<128,true,2><<<NAG/128, 256, SM_T128>>>(noise, hag, WH3, WL3, b_aggr_u, meanU);
    // 5) conv1 user: hu2 = relu((relu(hu@W_self_u+b) + meanU) @ W_comb_u + b)
    gemm_dual<64,false,4><<<NUSER/64, 256, SM_T64>>>(hu, nullptr, WH4, WL4, b_self_u,
                                                     meanU, WH5, WL5, b_comb_u, hu2);
    // 6) conv2: meanA = mean16(relu(hu2 @ W_aggr_a + b))
    gemm_aggr<64,false,1><<<NUSER/64, 256, SM_T64>>>(hu2, nullptr, WH0, WL0, b_aggr_a, meanA);
    // 7) conv2 agent + final projection + normalize -> out
    gemm_triple<<<NAG/128, 256, SM_T128>>>(ha2, WH1, WL1, b_self_a, meanA,
                                           WH2, WL2, b_comb_a, WH6, WL6, b_norm, out);
}